// round 1
// baseline (speedup 1.0000x reference)
#include <cuda_runtime.h>
#include <cuda_bf16.h>
#include <cstdint>

// PointPillarsScatter: out[B, C=64, NY=512, NX=512] <- scatter of feat[P, 64]
// at unique cells given by coords[P, 4] = (b, z, y, x).
//
// Strategy: invert the scatter into a gather.
//   K1: idx_map[cell] = -1 for all B*NY*NX cells
//   K2: idx_map[b*NY*NX + y*NX + x] = p       (unique cells guaranteed)
//   K3: per-CTA tile of 128 consecutive cells:
//         - gather feature rows (coalesced 256B reads) into smem [64][129]
//         - write out channel-major, 128 contiguous floats per channel
//       This makes the 256MB output write fully coalesced and doubles as the
//       zero-fill (empty cells write 0).

#define NYv 512
#define NXv 512
#define Cv 64
#define CELLS_PER_B (NYv * NXv)
#define MAX_B 4
#define TILE 128

// 4 MB scratch index map (device-global — no allocations allowed).
__device__ int g_idx[MAX_B * CELLS_PER_B];

__global__ void k_init_idx(int ncells4) {
    int i = blockIdx.x * blockDim.x + threadIdx.x;
    if (i < ncells4) {
        ((int4*)g_idx)[i] = make_int4(-1, -1, -1, -1);
    }
}

__global__ void k_scatter_idx(const int4* __restrict__ coords, int P) {
    int p = blockIdx.x * blockDim.x + threadIdx.x;
    if (p < P) {
        int4 c = coords[p];  // (b, z, y, x)
        int flat = c.x * CELLS_PER_B + c.z * NXv + c.w;
        g_idx[flat] = p;
    }
}

__global__ __launch_bounds__(256) void k_gather(
    const float* __restrict__ feat,
    float* __restrict__ out)
{
    // smem tile: [channel][cell-in-tile], padded to 129 so that the
    // transposed store (consecutive lanes -> consecutive channels, stride 129)
    // is bank-conflict-free (129 mod 32 == 1).
    __shared__ float tile[Cv][TILE + 1];

    const int cell_base = blockIdx.x * TILE;
    const int warp = threadIdx.x >> 5;
    const int lane = threadIdx.x & 31;

    // ---- Phase 1: gather 16 cells per warp ----
    // Preload this warp's 16 cell indices into lanes 0..15, then shfl.
    int p_l = -1;
    if (lane < 16) p_l = g_idx[cell_base + warp * 16 + lane];

    #pragma unroll
    for (int jj = 0; jj < 16; ++jj) {
        int p = __shfl_sync(0xffffffffu, p_l, jj);
        int j = warp * 16 + jj;
        float v0 = 0.0f, v1 = 0.0f;
        if (p >= 0) {
            const float* row = feat + (size_t)p * Cv;
            v0 = row[lane];        // 128B coalesced
            v1 = row[lane + 32];   // 128B coalesced
        }
        tile[lane][j]      = v0;   // conflict-free (stride 129)
        tile[lane + 32][j] = v1;
    }

    __syncthreads();

    // ---- Phase 2: coalesced channel-major write-out ----
    const int b  = cell_base / CELLS_PER_B;
    const int yx = cell_base % CELLS_PER_B;   // tile never crosses a batch (CELLS_PER_B % TILE == 0)
    float* outb = out + (size_t)b * Cv * CELLS_PER_B + yx;

    #pragma unroll
    for (int k = 0; k < (Cv * TILE) / 256; ++k) {  // 32 iterations
        int flat = k * 256 + threadIdx.x;
        int c = flat >> 7;        // /128
        int j = flat & (TILE - 1);
        outb[(size_t)c * CELLS_PER_B + j] = tile[c][j];
    }
}

extern "C" void kernel_launch(void* const* d_in, const int* in_sizes, int n_in,
                              void* d_out, int out_size) {
    const float* feat   = (const float*)d_in[0];
    const int4*  coords = (const int4*)d_in[1];
    // d_in[2] is batch_size on device; derive B from out_size instead.

    const int P = in_sizes[0] / Cv;
    const int B = out_size / (Cv * CELLS_PER_B);
    const int ncells = B * CELLS_PER_B;

    // K1: init index map (-1). ncells divisible by 1024.
    k_init_idx<<<(ncells / 4 + 255) / 256, 256>>>(ncells / 4);

    // K2: scatter point ids.
    k_scatter_idx<<<(P + 255) / 256, 256>>>(coords, P);

    // K3: gather + transpose + coalesced write (also zero-fills).
    k_gather<<<ncells / TILE, 256>>>(feat, (float*)d_out);
}